// round 14
// baseline (speedup 1.0000x reference)
#include <cuda_runtime.h>
#include <cuda_bf16.h>
#include <cuda_pipeline.h>
#include <mma.h>
#include <math.h>

#define B_    8
#define C_    256
#define NPIX  4096
#define SROW  40
#define FST   68
#define WPAD  40
#define XPAD  264

using namespace nvcuda;

// q hi rows [0,32), k hi [32,64), q lo [64,96), k lo [96,128)
__device__ __nv_bfloat16  g_qkb[(size_t)B_ * 128 * NPIX];
__device__ __nv_bfloat16  g_vb[(size_t)B_ * C_ * NPIX];
__device__ __nv_bfloat16  g_attb[(size_t)B_ * NPIX * NPIX];

// ---------------------------------------------------------------------------
// K1: QKV projection on tensor cores via split-bf16 (R13, unchanged).
// ---------------------------------------------------------------------------
__global__ void __launch_bounds__(256)
proj_kernel(const float* __restrict__ x,
            const float* __restrict__ Wq, const float* __restrict__ bq,
            const float* __restrict__ Wk, const float* __restrict__ bk,
            const float* __restrict__ Wv, const float* __restrict__ bv) {
    __shared__ __align__(16) __nv_bfloat16 Whi[64 * WPAD];
    __shared__ __align__(16) __nv_bfloat16 Wlo[64 * WPAD];
    __shared__ __align__(16) __nv_bfloat16 Xhi[32 * XPAD];
    __shared__ __align__(16) __nv_bfloat16 Xlo[32 * XPAD];

    const int b  = blockIdx.z;
    const int o0 = blockIdx.y * 64;
    const int n0 = blockIdx.x * 256;
    const int tid  = threadIdx.x;
    const int warp = tid >> 5;
    const int lane = tid & 31;
    const int wo = (warp & 1) * 32;
    const int wn = (warp >> 1) * 64;

    const float* xb = x + (size_t)b * C_ * NPIX;

    wmma::fragment<wmma::accumulator, 16, 16, 16, float> acc[2][4];
    #pragma unroll
    for (int i = 0; i < 2; ++i) {
        #pragma unroll
        for (int j = 0; j < 4; ++j) wmma::fill_fragment(acc[i][j], 0.0f);
    }

    for (int k0 = 0; k0 < C_; k0 += 32) {
        {
            const int wrow = tid >> 2;
            const int wk = (tid & 3) * 8;
            const int go = o0 + wrow;
            const float* Wrow;
            if (go < 32) {
                Wrow = Wq + go * C_;
            } else if (go < 64) {
                Wrow = Wk + (go - 32) * C_;
            } else {
                Wrow = Wv + (go - 64) * C_;
            }
            #pragma unroll
            for (int u = 0; u < 8; ++u) {
                float v = Wrow[k0 + wk + u];
                __nv_bfloat16 h = __float2bfloat16(v);
                Whi[wrow * WPAD + wk + u] = h;
                Wlo[wrow * WPAD + wk + u] = __float2bfloat16(v - __bfloat162float(h));
            }
        }
        {
            const int kk = tid >> 3;
            const int nj = (tid & 7) * 32;
            const float* xr = xb + (size_t)(k0 + kk) * NPIX + n0 + nj;
            __nv_bfloat16* dh = &Xhi[kk * XPAD + nj];
            __nv_bfloat16* dl = &Xlo[kk * XPAD + nj];
            #pragma unroll
            for (int u = 0; u < 8; ++u) {
                float4 v4 = *(const float4*)(xr + u * 4);
                float vv[4];
                vv[0] = v4.x; vv[1] = v4.y; vv[2] = v4.z; vv[3] = v4.w;
                #pragma unroll
                for (int e = 0; e < 4; ++e) {
                    __nv_bfloat16 h = __float2bfloat16(vv[e]);
                    dh[u * 4 + e] = h;
                    dl[u * 4 + e] = __float2bfloat16(vv[e] - __bfloat162float(h));
                }
            }
        }
        __syncthreads();

        #pragma unroll
        for (int kc = 0; kc < 2; ++kc) {
            wmma::fragment<wmma::matrix_a, 16, 16, 16, __nv_bfloat16, wmma::row_major> ah[2], al[2];
            wmma::fragment<wmma::matrix_b, 16, 16, 16, __nv_bfloat16, wmma::row_major> bh[4], bl[4];
            #pragma unroll
            for (int i = 0; i < 2; ++i) {
                wmma::load_matrix_sync(ah[i], &Whi[(wo + 16 * i) * WPAD + kc * 16], WPAD);
                wmma::load_matrix_sync(al[i], &Wlo[(wo + 16 * i) * WPAD + kc * 16], WPAD);
            }
            #pragma unroll
            for (int j = 0; j < 4; ++j) {
                wmma::load_matrix_sync(bh[j], &Xhi[(kc * 16) * XPAD + wn + 16 * j], XPAD);
                wmma::load_matrix_sync(bl[j], &Xlo[(kc * 16) * XPAD + wn + 16 * j], XPAD);
            }
            #pragma unroll
            for (int i = 0; i < 2; ++i) {
                #pragma unroll
                for (int j = 0; j < 4; ++j) {
                    wmma::mma_sync(acc[i][j], ah[i], bl[j], acc[i][j]);
                    wmma::mma_sync(acc[i][j], al[i], bh[j], acc[i][j]);
                    wmma::mma_sync(acc[i][j], ah[i], bh[j], acc[i][j]);
                }
            }
        }
        __syncthreads();
    }

    float* stg = (float*)Xhi + warp * 256;
    const int srow = lane >> 1;
    const int scol = (lane & 1) * 8;

    #pragma unroll
    for (int i = 0; i < 2; ++i) {
        #pragma unroll
        for (int j = 0; j < 4; ++j) {
            wmma::store_matrix_sync(stg, acc[i][j], 16, wmma::mem_row_major);
            __syncwarp();
            const int o = o0 + wo + 16 * i + srow;
            float bias;
            if (o < 32) {
                bias = bq[o];
            } else if (o < 64) {
                bias = bk[o - 32];
            } else {
                bias = bv[o - 64];
            }
            const int nn = n0 + wn + 16 * j + scol;
            if (o < 64) {
                __nv_bfloat16* dhi = g_qkb + ((size_t)b * 128 + o) * NPIX + nn;
                __nv_bfloat16* dlo = dhi + (size_t)64 * NPIX;
                __align__(16) __nv_bfloat16 hv[8];
                __align__(16) __nv_bfloat16 lv[8];
                #pragma unroll
                for (int e = 0; e < 8; ++e) {
                    float val = stg[srow * 16 + scol + e] + bias;
                    __nv_bfloat16 h = __float2bfloat16(val);
                    hv[e] = h;
                    lv[e] = __float2bfloat16(val - __bfloat162float(h));
                }
                *(uint4*)dhi = *(const uint4*)hv;
                *(uint4*)dlo = *(const uint4*)lv;
            } else {
                __nv_bfloat16* dst = g_vb + ((size_t)b * C_ + (o - 64)) * NPIX + nn;
                __align__(16) __nv_bfloat16 hv[8];
                #pragma unroll
                for (int e = 0; e < 8; ++e) {
                    hv[e] = __float2bfloat16(stg[srow * 16 + scol + e] + bias);
                }
                *(uint4*)dst = *(const uint4*)hv;
            }
            __syncwarp();
        }
    }
}

// ---------------------------------------------------------------------------
// K2: FUSED energy + softmax v2 (R12, unchanged).
// ---------------------------------------------------------------------------
__global__ void __launch_bounds__(256, 2)
fused_attn_kernel(float* __restrict__ att) {
    __shared__ __align__(16) float stage[8][32 * FST];
    __shared__ float partsum[8][32];
    __shared__ float rowinv[128];

    const int b  = blockIdx.y;
    const int n0 = blockIdx.x * 128;
    const int warp = threadIdx.x >> 5;
    const int lane = threadIdx.x & 31;
    const int wn = (warp & 3) * 32;
    const int wm = (warp >> 2) * 64;

    const __nv_bfloat16* qh = g_qkb + (size_t)b * 128 * NPIX;
    const __nv_bfloat16* kh = qh + (size_t)32 * NPIX;
    const __nv_bfloat16* ql = qh + (size_t)64 * NPIX;
    const __nv_bfloat16* kl = qh + (size_t)96 * NPIX;

    float* st = stage[warp];

    wmma::fragment<wmma::matrix_a, 16, 16, 16, __nv_bfloat16, wmma::col_major> ah[2][2], al[2][2];
    #pragma unroll
    for (int ks = 0; ks < 2; ++ks) {
        #pragma unroll
        for (int i = 0; i < 2; ++i) {
            wmma::load_matrix_sync(ah[ks][i], qh + (size_t)(ks * 16) * NPIX + n0 + wn + 16 * i, NPIX);
            wmma::load_matrix_sync(al[ks][i], ql + (size_t)(ks * 16) * NPIX + n0 + wn + 16 * i, NPIX);
        }
    }

    float rs = 0.f;
    for (int mt = 0; mt < 32; ++mt) {
        const int m0 = mt * 128;
        wmma::fragment<wmma::accumulator, 16, 16, 16, float> acc[2][4];
        #pragma unroll
        for (int i = 0; i < 2; ++i) {
            #pragma unroll
            for (int j = 0; j < 4; ++j) wmma::fill_fragment(acc[i][j], 0.0f);
        }
        #pragma unroll
        for (int ks = 0; ks < 2; ++ks) {
            wmma::fragment<wmma::matrix_b, 16, 16, 16, __nv_bfloat16, wmma::row_major> bh[4], bl[4];
            #pragma unroll
            for (int j = 0; j < 4; ++j) {
                wmma::load_matrix_sync(bh[j], kh + (size_t)(ks * 16) * NPIX + m0 + wm + 16 * j, NPIX);
                wmma::load_matrix_sync(bl[j], kl + (size_t)(ks * 16) * NPIX + m0 + wm + 16 * j, NPIX);
            }
            #pragma unroll
            for (int i = 0; i < 2; ++i) {
                #pragma unroll
                for (int j = 0; j < 4; ++j) {
                    wmma::mma_sync(acc[i][j], ah[ks][i], bl[j], acc[i][j]);
                    wmma::mma_sync(acc[i][j], al[ks][i], bh[j], acc[i][j]);
                    wmma::mma_sync(acc[i][j], ah[ks][i], bh[j], acc[i][j]);
                }
            }
        }
        #pragma unroll
        for (int i = 0; i < 2; ++i) {
            #pragma unroll
            for (int j = 0; j < 4; ++j) {
                wmma::store_matrix_sync(st + (16 * i) * FST + 16 * j, acc[i][j],
                                        FST, wmma::mem_row_major);
            }
        }
        __syncwarp();
        const float* srow = st + lane * FST;
        int c = lane & 31;
        #pragma unroll
        for (int s = 0; s < 32; ++s) {
            rs += __expf(srow[c]) + __expf(srow[32 + c]);
            c = (c + 1) & 31;
        }
        __syncwarp();
    }
    partsum[warp][lane] = rs;
    __syncthreads();
    if (warp < 4) {
        float tot = partsum[warp][lane] + partsum[warp + 4][lane];
        rowinv[wn + lane] = 1.0f / tot;
    }
    __syncthreads();

    float* ab = att + ((size_t)b * NPIX + n0) * NPIX;
    __nv_bfloat16* abb = g_attb + ((size_t)b * NPIX + n0) * NPIX;

    for (int mt = 0; mt < 32; ++mt) {
        const int m0 = mt * 128;
        wmma::fragment<wmma::accumulator, 16, 16, 16, float> acc[2][4];
        #pragma unroll
        for (int i = 0; i < 2; ++i) {
            #pragma unroll
            for (int j = 0; j < 4; ++j) wmma::fill_fragment(acc[i][j], 0.0f);
        }
        #pragma unroll
        for (int ks = 0; ks < 2; ++ks) {
            wmma::fragment<wmma::matrix_b, 16, 16, 16, __nv_bfloat16, wmma::row_major> bh[4], bl[4];
            #pragma unroll
            for (int j = 0; j < 4; ++j) {
                wmma::load_matrix_sync(bh[j], kh + (size_t)(ks * 16) * NPIX + m0 + wm + 16 * j, NPIX);
                wmma::load_matrix_sync(bl[j], kl + (size_t)(ks * 16) * NPIX + m0 + wm + 16 * j, NPIX);
            }
            #pragma unroll
            for (int i = 0; i < 2; ++i) {
                #pragma unroll
                for (int j = 0; j < 4; ++j) {
                    wmma::mma_sync(acc[i][j], ah[ks][i], bl[j], acc[i][j]);
                    wmma::mma_sync(acc[i][j], al[ks][i], bh[j], acc[i][j]);
                    wmma::mma_sync(acc[i][j], ah[ks][i], bh[j], acc[i][j]);
                }
            }
        }
        #pragma unroll
        for (int i = 0; i < 2; ++i) {
            #pragma unroll
            for (int j = 0; j < 4; ++j) {
                wmma::store_matrix_sync(st + (16 * i) * FST + 16 * j, acc[i][j],
                                        FST, wmma::mem_row_major);
            }
        }
        __syncwarp();
        #pragma unroll 4
        for (int r = 0; r < 32; ++r) {
            const float inv = rowinv[wn + r];
            const float e0 = st[r * FST + 2 * lane];
            const float e1 = st[r * FST + 2 * lane + 1];
            const float p0 = __expf(e0) * inv;
            const float p1 = __expf(e1) * inv;
            const size_t off = (size_t)(wn + r) * NPIX + m0 + wm + 2 * lane;
            float2 pv;
            pv.x = p0;
            pv.y = p1;
            *(float2*)&ab[off] = pv;
            *(__nv_bfloat162*)&abb[off] = __floats2bfloat162_rn(p0, p1);
        }
        __syncwarp();
    }
}

// ---------------------------------------------------------------------------
// K3: tensor-core AV GEMM, 3-stage cp.async ring, one barrier per iteration.
// Grid: x=c-tiles (2), y=n-tiles (32) so the c-pair sharing an att n-tile is
// launch-adjacent -> second att read is L2-resident.
// ---------------------------------------------------------------------------
__global__ void __launch_bounds__(256, 2)
av_wmma_kernel(const float* __restrict__ x, const float* __restrict__ gamma,
               float* __restrict__ out) {
    __shared__ __align__(256) __nv_bfloat16 As[3][128 * SROW];
    __shared__ __align__(256) __nv_bfloat16 Bs[3][128 * SROW];

    const int b    = blockIdx.z;
    const int c0   = blockIdx.x * 128;
    const int n0   = blockIdx.y * 128;
    const int tid  = threadIdx.x;
    const int warp = tid >> 5;
    const int lane = tid & 31;
    const int wc   = (warp & 3) * 32;
    const int wn   = (warp >> 2) * 64;

    const __nv_bfloat16* vb = g_vb   + (size_t)b * C_ * NPIX;
    const __nv_bfloat16* ab = g_attb + (size_t)b * NPIX * NPIX;

    const int lrow  = tid >> 1;
    const int lhalf = (tid & 1) * 16;
    const __nv_bfloat16* gA = vb + (size_t)(c0 + lrow) * NPIX + lhalf;
    const __nv_bfloat16* gB = ab + (size_t)(n0 + lrow) * NPIX + lhalf;
    const int sOff = lrow * SROW + lhalf;

    wmma::fragment<wmma::accumulator, 16, 16, 16, float> acc[2][4];
    #pragma unroll
    for (int i = 0; i < 2; ++i) {
        #pragma unroll
        for (int j = 0; j < 4; ++j) wmma::fill_fragment(acc[i][j], 0.0f);
    }

    // Prologue: stages 0 and 1.
    #pragma unroll
    for (int s = 0; s < 2; ++s) {
        const __nv_bfloat16* pA = gA + s * 32;
        const __nv_bfloat16* pB = gB + s * 32;
        __pipeline_memcpy_async(&As[s][sOff],     pA,     16);
        __pipeline_memcpy_async(&As[s][sOff + 8], pA + 8, 16);
        __pipeline_memcpy_async(&Bs[s][sOff],     pB,     16);
        __pipeline_memcpy_async(&Bs[s][sOff + 8], pB + 8, 16);
        __pipeline_commit();
    }

    int bufc = 0;   // buffer for current compute stage
    int bufw = 2;   // buffer for next issued stage
    for (int it = 0; it < 128; ++it) {
        __pipeline_wait_prior(1);
        __syncthreads();

        if (it + 2 < 128) {
            const __nv_bfloat16* pA = gA + (it + 2) * 32;
            const __nv_bfloat16* pB = gB + (it + 2) * 32;
            __pipeline_memcpy_async(&As[bufw][sOff],     pA,     16);
            __pipeline_memcpy_async(&As[bufw][sOff + 8], pA + 8, 16);
            __pipeline_memcpy_async(&Bs[bufw][sOff],     pB,     16);
            __pipeline_memcpy_async(&Bs[bufw][sOff + 8], pB + 8, 16);
        }
        __pipeline_commit();

        const __nv_bfloat16* Ab = &As[bufc][0];
        const __nv_bfloat16* Bb = &Bs[bufc][0];

        #pragma unroll
        for (int kk = 0; kk < 32; kk += 16) {
            wmma::fragment<wmma::matrix_a, 16, 16, 16, __nv_bfloat16, wmma::row_major> afrag[2];
            wmma::fragment<wmma::matrix_b, 16, 16, 16, __nv_bfloat16, wmma::col_major> bfrag[4];
            #pragma unroll
            for (int i = 0; i < 2; ++i) {
                wmma::load_matrix_sync(afrag[i], Ab + (wc + 16 * i) * SROW + kk, SROW);
            }
            #pragma unroll
            for (int j = 0; j < 4; ++j) {
                wmma::load_matrix_sync(bfrag[j], Bb + (wn + 16 * j) * SROW + kk, SROW);
            }
            #pragma unroll
            for (int i = 0; i < 2; ++i) {
                #pragma unroll
                for (int j = 0; j < 4; ++j) {
                    wmma::mma_sync(acc[i][j], afrag[i], bfrag[j], acc[i][j]);
                }
            }
        }

        bufc = (bufc + 1 == 3) ? 0 : bufc + 1;
        bufw = (bufw + 1 == 3) ? 0 : bufw + 1;
    }
    __syncthreads();

    const float g = 0.5f * gamma[0];
    const float* xb = x   + (size_t)b * C_ * NPIX;
    float*       ob = out + (size_t)b * C_ * NPIX;
    float* stg = (float*)(&As[0][0]) + warp * 256;

    const int srow = lane >> 1;
    const int scol = (lane & 1) * 8;

    #pragma unroll
    for (int i = 0; i < 2; ++i) {
        #pragma unroll
        for (int j = 0; j < 4; ++j) {
            wmma::store_matrix_sync(stg, acc[i][j], 16, wmma::mem_row_major);
            __syncwarp();
            const int cc = c0 + wc + 16 * i + srow;
            const int nn = n0 + wn + 16 * j + scol;
            const size_t off = (size_t)cc * NPIX + nn;
            float4 s0 = *(const float4*)&stg[srow * 16 + scol];
            float4 s1 = *(const float4*)&stg[srow * 16 + scol + 4];
            float4 xv0 = *(const float4*)&xb[off];
            float4 xv1 = *(const float4*)&xb[off + 4];
            float4 ov0;
            float4 ov1;
            ov0.x = g * s0.x + xv0.x;
            ov0.y = g * s0.y + xv0.y;
            ov0.z = g * s0.z + xv0.z;
            ov0.w = g * s0.w + xv0.w;
            ov1.x = g * s1.x + xv1.x;
            ov1.y = g * s1.y + xv1.y;
            ov1.z = g * s1.z + xv1.z;
            ov1.w = g * s1.w + xv1.w;
            *(float4*)&ob[off]     = ov0;
            *(float4*)&ob[off + 4] = ov1;
            __syncwarp();
        }
    }
}

// ---------------------------------------------------------------------------
extern "C" void kernel_launch(void* const* d_in, const int* in_sizes, int n_in,
                              void* d_out, int out_size) {
    const float* x     = (const float*)d_in[0];
    const float* Wq    = (const float*)d_in[1];
    const float* bq    = (const float*)d_in[2];
    const float* Wk    = (const float*)d_in[3];
    const float* bk    = (const float*)d_in[4];
    const float* Wv    = (const float*)d_in[5];
    const float* bv    = (const float*)d_in[6];
    const float* gamma = (const float*)d_in[7];

    float* out = (float*)d_out;
    float* att = out + (size_t)B_ * C_ * NPIX;

    proj_kernel<<<dim3(16, 5, B_), 256>>>(x, Wq, bq, Wk, bk, Wv, bv);
    fused_attn_kernel<<<dim3(32, B_), 256>>>(att);
    av_wmma_kernel<<<dim3(2, 32, B_), 256>>>(x, gamma, out);
}

// round 15
// speedup vs baseline: 1.0535x; 1.0535x over previous
#include <cuda_runtime.h>
#include <cuda_bf16.h>
#include <cuda_pipeline.h>
#include <mma.h>
#include <math.h>

#define B_    8
#define C_    256
#define NPIX  4096
#define SROW  40
#define FST   68
#define WPAD  40
#define XPAD  264

using namespace nvcuda;

// q hi rows [0,32), k hi [32,64), q lo [64,96), k lo [96,128)
__device__ __nv_bfloat16  g_qkb[(size_t)B_ * 128 * NPIX];
__device__ __nv_bfloat16  g_vb[(size_t)B_ * C_ * NPIX];
__device__ __nv_bfloat16  g_attb[(size_t)B_ * NPIX * NPIX];

// ---------------------------------------------------------------------------
// K1: QKV projection on tensor cores via split-bf16 (R13 + occupancy-2 cap).
// ---------------------------------------------------------------------------
__global__ void __launch_bounds__(256, 2)
proj_kernel(const float* __restrict__ x,
            const float* __restrict__ Wq, const float* __restrict__ bq,
            const float* __restrict__ Wk, const float* __restrict__ bk,
            const float* __restrict__ Wv, const float* __restrict__ bv) {
    __shared__ __align__(16) __nv_bfloat16 Whi[64 * WPAD];
    __shared__ __align__(16) __nv_bfloat16 Wlo[64 * WPAD];
    __shared__ __align__(16) __nv_bfloat16 Xhi[32 * XPAD];
    __shared__ __align__(16) __nv_bfloat16 Xlo[32 * XPAD];

    const int b  = blockIdx.z;
    const int o0 = blockIdx.y * 64;
    const int n0 = blockIdx.x * 256;
    const int tid  = threadIdx.x;
    const int warp = tid >> 5;
    const int lane = tid & 31;
    const int wo = (warp & 1) * 32;
    const int wn = (warp >> 1) * 64;

    const float* xb = x + (size_t)b * C_ * NPIX;

    wmma::fragment<wmma::accumulator, 16, 16, 16, float> acc[2][4];
    #pragma unroll
    for (int i = 0; i < 2; ++i) {
        #pragma unroll
        for (int j = 0; j < 4; ++j) wmma::fill_fragment(acc[i][j], 0.0f);
    }

    for (int k0 = 0; k0 < C_; k0 += 32) {
        {
            const int wrow = tid >> 2;
            const int wk = (tid & 3) * 8;
            const int go = o0 + wrow;
            const float* Wrow;
            if (go < 32) {
                Wrow = Wq + go * C_;
            } else if (go < 64) {
                Wrow = Wk + (go - 32) * C_;
            } else {
                Wrow = Wv + (go - 64) * C_;
            }
            #pragma unroll
            for (int u = 0; u < 8; ++u) {
                float v = Wrow[k0 + wk + u];
                __nv_bfloat16 h = __float2bfloat16(v);
                Whi[wrow * WPAD + wk + u] = h;
                Wlo[wrow * WPAD + wk + u] = __float2bfloat16(v - __bfloat162float(h));
            }
        }
        {
            const int kk = tid >> 3;
            const int nj = (tid & 7) * 32;
            const float* xr = xb + (size_t)(k0 + kk) * NPIX + n0 + nj;
            __nv_bfloat16* dh = &Xhi[kk * XPAD + nj];
            __nv_bfloat16* dl = &Xlo[kk * XPAD + nj];
            #pragma unroll
            for (int u = 0; u < 8; ++u) {
                float4 v4 = *(const float4*)(xr + u * 4);
                float vv[4];
                vv[0] = v4.x; vv[1] = v4.y; vv[2] = v4.z; vv[3] = v4.w;
                #pragma unroll
                for (int e = 0; e < 4; ++e) {
                    __nv_bfloat16 h = __float2bfloat16(vv[e]);
                    dh[u * 4 + e] = h;
                    dl[u * 4 + e] = __float2bfloat16(vv[e] - __bfloat162float(h));
                }
            }
        }
        __syncthreads();

        #pragma unroll
        for (int kc = 0; kc < 2; ++kc) {
            wmma::fragment<wmma::matrix_a, 16, 16, 16, __nv_bfloat16, wmma::row_major> ah[2], al[2];
            wmma::fragment<wmma::matrix_b, 16, 16, 16, __nv_bfloat16, wmma::row_major> bh[4], bl[4];
            #pragma unroll
            for (int i = 0; i < 2; ++i) {
                wmma::load_matrix_sync(ah[i], &Whi[(wo + 16 * i) * WPAD + kc * 16], WPAD);
                wmma::load_matrix_sync(al[i], &Wlo[(wo + 16 * i) * WPAD + kc * 16], WPAD);
            }
            #pragma unroll
            for (int j = 0; j < 4; ++j) {
                wmma::load_matrix_sync(bh[j], &Xhi[(kc * 16) * XPAD + wn + 16 * j], XPAD);
                wmma::load_matrix_sync(bl[j], &Xlo[(kc * 16) * XPAD + wn + 16 * j], XPAD);
            }
            #pragma unroll
            for (int i = 0; i < 2; ++i) {
                #pragma unroll
                for (int j = 0; j < 4; ++j) {
                    wmma::mma_sync(acc[i][j], ah[i], bl[j], acc[i][j]);
                    wmma::mma_sync(acc[i][j], al[i], bh[j], acc[i][j]);
                    wmma::mma_sync(acc[i][j], ah[i], bh[j], acc[i][j]);
                }
            }
        }
        __syncthreads();
    }

    float* stg = (float*)Xhi + warp * 256;
    const int srow = lane >> 1;
    const int scol = (lane & 1) * 8;

    #pragma unroll
    for (int i = 0; i < 2; ++i) {
        #pragma unroll
        for (int j = 0; j < 4; ++j) {
            wmma::store_matrix_sync(stg, acc[i][j], 16, wmma::mem_row_major);
            __syncwarp();
            const int o = o0 + wo + 16 * i + srow;
            float bias;
            if (o < 32) {
                bias = bq[o];
            } else if (o < 64) {
                bias = bk[o - 32];
            } else {
                bias = bv[o - 64];
            }
            const int nn = n0 + wn + 16 * j + scol;
            if (o < 64) {
                __nv_bfloat16* dhi = g_qkb + ((size_t)b * 128 + o) * NPIX + nn;
                __nv_bfloat16* dlo = dhi + (size_t)64 * NPIX;
                __align__(16) __nv_bfloat16 hv[8];
                __align__(16) __nv_bfloat16 lv[8];
                #pragma unroll
                for (int e = 0; e < 8; ++e) {
                    float val = stg[srow * 16 + scol + e] + bias;
                    __nv_bfloat16 h = __float2bfloat16(val);
                    hv[e] = h;
                    lv[e] = __float2bfloat16(val - __bfloat162float(h));
                }
                *(uint4*)dhi = *(const uint4*)hv;
                *(uint4*)dlo = *(const uint4*)lv;
            } else {
                __nv_bfloat16* dst = g_vb + ((size_t)b * C_ + (o - 64)) * NPIX + nn;
                __align__(16) __nv_bfloat16 hv[8];
                #pragma unroll
                for (int e = 0; e < 8; ++e) {
                    hv[e] = __float2bfloat16(stg[srow * 16 + scol + e] + bias);
                }
                *(uint4*)dst = *(const uint4*)hv;
            }
            __syncwarp();
        }
    }
}

// ---------------------------------------------------------------------------
// K2: FUSED energy + softmax v2 (R12, unchanged).
// ---------------------------------------------------------------------------
__global__ void __launch_bounds__(256, 2)
fused_attn_kernel(float* __restrict__ att) {
    __shared__ __align__(16) float stage[8][32 * FST];
    __shared__ float partsum[8][32];
    __shared__ float rowinv[128];

    const int b  = blockIdx.y;
    const int n0 = blockIdx.x * 128;
    const int warp = threadIdx.x >> 5;
    const int lane = threadIdx.x & 31;
    const int wn = (warp & 3) * 32;
    const int wm = (warp >> 2) * 64;

    const __nv_bfloat16* qh = g_qkb + (size_t)b * 128 * NPIX;
    const __nv_bfloat16* kh = qh + (size_t)32 * NPIX;
    const __nv_bfloat16* ql = qh + (size_t)64 * NPIX;
    const __nv_bfloat16* kl = qh + (size_t)96 * NPIX;

    float* st = stage[warp];

    wmma::fragment<wmma::matrix_a, 16, 16, 16, __nv_bfloat16, wmma::col_major> ah[2][2], al[2][2];
    #pragma unroll
    for (int ks = 0; ks < 2; ++ks) {
        #pragma unroll
        for (int i = 0; i < 2; ++i) {
            wmma::load_matrix_sync(ah[ks][i], qh + (size_t)(ks * 16) * NPIX + n0 + wn + 16 * i, NPIX);
            wmma::load_matrix_sync(al[ks][i], ql + (size_t)(ks * 16) * NPIX + n0 + wn + 16 * i, NPIX);
        }
    }

    float rs = 0.f;
    for (int mt = 0; mt < 32; ++mt) {
        const int m0 = mt * 128;
        wmma::fragment<wmma::accumulator, 16, 16, 16, float> acc[2][4];
        #pragma unroll
        for (int i = 0; i < 2; ++i) {
            #pragma unroll
            for (int j = 0; j < 4; ++j) wmma::fill_fragment(acc[i][j], 0.0f);
        }
        #pragma unroll
        for (int ks = 0; ks < 2; ++ks) {
            wmma::fragment<wmma::matrix_b, 16, 16, 16, __nv_bfloat16, wmma::row_major> bh[4], bl[4];
            #pragma unroll
            for (int j = 0; j < 4; ++j) {
                wmma::load_matrix_sync(bh[j], kh + (size_t)(ks * 16) * NPIX + m0 + wm + 16 * j, NPIX);
                wmma::load_matrix_sync(bl[j], kl + (size_t)(ks * 16) * NPIX + m0 + wm + 16 * j, NPIX);
            }
            #pragma unroll
            for (int i = 0; i < 2; ++i) {
                #pragma unroll
                for (int j = 0; j < 4; ++j) {
                    wmma::mma_sync(acc[i][j], ah[ks][i], bl[j], acc[i][j]);
                    wmma::mma_sync(acc[i][j], al[ks][i], bh[j], acc[i][j]);
                    wmma::mma_sync(acc[i][j], ah[ks][i], bh[j], acc[i][j]);
                }
            }
        }
        #pragma unroll
        for (int i = 0; i < 2; ++i) {
            #pragma unroll
            for (int j = 0; j < 4; ++j) {
                wmma::store_matrix_sync(st + (16 * i) * FST + 16 * j, acc[i][j],
                                        FST, wmma::mem_row_major);
            }
        }
        __syncwarp();
        const float* srow = st + lane * FST;
        int c = lane & 31;
        #pragma unroll
        for (int s = 0; s < 32; ++s) {
            rs += __expf(srow[c]) + __expf(srow[32 + c]);
            c = (c + 1) & 31;
        }
        __syncwarp();
    }
    partsum[warp][lane] = rs;
    __syncthreads();
    if (warp < 4) {
        float tot = partsum[warp][lane] + partsum[warp + 4][lane];
        rowinv[wn + lane] = 1.0f / tot;
    }
    __syncthreads();

    float* ab = att + ((size_t)b * NPIX + n0) * NPIX;
    __nv_bfloat16* abb = g_attb + ((size_t)b * NPIX + n0) * NPIX;

    for (int mt = 0; mt < 32; ++mt) {
        const int m0 = mt * 128;
        wmma::fragment<wmma::accumulator, 16, 16, 16, float> acc[2][4];
        #pragma unroll
        for (int i = 0; i < 2; ++i) {
            #pragma unroll
            for (int j = 0; j < 4; ++j) wmma::fill_fragment(acc[i][j], 0.0f);
        }
        #pragma unroll
        for (int ks = 0; ks < 2; ++ks) {
            wmma::fragment<wmma::matrix_b, 16, 16, 16, __nv_bfloat16, wmma::row_major> bh[4], bl[4];
            #pragma unroll
            for (int j = 0; j < 4; ++j) {
                wmma::load_matrix_sync(bh[j], kh + (size_t)(ks * 16) * NPIX + m0 + wm + 16 * j, NPIX);
                wmma::load_matrix_sync(bl[j], kl + (size_t)(ks * 16) * NPIX + m0 + wm + 16 * j, NPIX);
            }
            #pragma unroll
            for (int i = 0; i < 2; ++i) {
                #pragma unroll
                for (int j = 0; j < 4; ++j) {
                    wmma::mma_sync(acc[i][j], ah[ks][i], bl[j], acc[i][j]);
                    wmma::mma_sync(acc[i][j], al[ks][i], bh[j], acc[i][j]);
                    wmma::mma_sync(acc[i][j], ah[ks][i], bh[j], acc[i][j]);
                }
            }
        }
        #pragma unroll
        for (int i = 0; i < 2; ++i) {
            #pragma unroll
            for (int j = 0; j < 4; ++j) {
                wmma::store_matrix_sync(st + (16 * i) * FST + 16 * j, acc[i][j],
                                        FST, wmma::mem_row_major);
            }
        }
        __syncwarp();
        #pragma unroll 4
        for (int r = 0; r < 32; ++r) {
            const float inv = rowinv[wn + r];
            const float e0 = st[r * FST + 2 * lane];
            const float e1 = st[r * FST + 2 * lane + 1];
            const float p0 = __expf(e0) * inv;
            const float p1 = __expf(e1) * inv;
            const size_t off = (size_t)(wn + r) * NPIX + m0 + wm + 2 * lane;
            float2 pv;
            pv.x = p0;
            pv.y = p1;
            *(float2*)&ab[off] = pv;
            *(__nv_bfloat162*)&abb[off] = __floats2bfloat162_rn(p0, p1);
        }
        __syncwarp();
    }
}

// ---------------------------------------------------------------------------
// K3: tensor-core AV GEMM, cp.async double-buffered (R11 exact, 328us).
// ---------------------------------------------------------------------------
__global__ void __launch_bounds__(256, 2)
av_wmma_kernel(const float* __restrict__ x, const float* __restrict__ gamma,
               float* __restrict__ out) {
    __shared__ __align__(256) __nv_bfloat16 As[2][128 * SROW];
    __shared__ __align__(256) __nv_bfloat16 Bs[2][128 * SROW];

    const int b    = blockIdx.z;
    const int c0   = blockIdx.y * 128;
    const int n0   = blockIdx.x * 128;
    const int tid  = threadIdx.x;
    const int warp = tid >> 5;
    const int lane = tid & 31;
    const int wc   = (warp & 3) * 32;
    const int wn   = (warp >> 2) * 64;

    const __nv_bfloat16* vb = g_vb   + (size_t)b * C_ * NPIX;
    const __nv_bfloat16* ab = g_attb + (size_t)b * NPIX * NPIX;

    const int lrow  = tid >> 1;
    const int lhalf = (tid & 1) * 16;
    const __nv_bfloat16* gA = vb + (size_t)(c0 + lrow) * NPIX + lhalf;
    const __nv_bfloat16* gB = ab + (size_t)(n0 + lrow) * NPIX + lhalf;
    const int sOff = lrow * SROW + lhalf;

    wmma::fragment<wmma::accumulator, 16, 16, 16, float> acc[2][4];
    #pragma unroll
    for (int i = 0; i < 2; ++i) {
        #pragma unroll
        for (int j = 0; j < 4; ++j) wmma::fill_fragment(acc[i][j], 0.0f);
    }

    __pipeline_memcpy_async(&As[0][sOff],     gA,     16);
    __pipeline_memcpy_async(&As[0][sOff + 8], gA + 8, 16);
    __pipeline_memcpy_async(&Bs[0][sOff],     gB,     16);
    __pipeline_memcpy_async(&Bs[0][sOff + 8], gB + 8, 16);
    __pipeline_commit();

    for (int it = 0; it < 128; ++it) {
        const int cur = it & 1;
        const int nxt = cur ^ 1;
        if (it < 127) {
            const __nv_bfloat16* pA = gA + (it + 1) * 32;
            const __nv_bfloat16* pB = gB + (it + 1) * 32;
            __pipeline_memcpy_async(&As[nxt][sOff],     pA,     16);
            __pipeline_memcpy_async(&As[nxt][sOff + 8], pA + 8, 16);
            __pipeline_memcpy_async(&Bs[nxt][sOff],     pB,     16);
            __pipeline_memcpy_async(&Bs[nxt][sOff + 8], pB + 8, 16);
            __pipeline_commit();
            __pipeline_wait_prior(1);
        } else {
            __pipeline_wait_prior(0);
        }
        __syncthreads();

        const __nv_bfloat16* Ab = &As[cur][0];
        const __nv_bfloat16* Bb = &Bs[cur][0];

        #pragma unroll
        for (int kk = 0; kk < 32; kk += 16) {
            wmma::fragment<wmma::matrix_a, 16, 16, 16, __nv_bfloat16, wmma::row_major> afrag[2];
            wmma::fragment<wmma::matrix_b, 16, 16, 16, __nv_bfloat16, wmma::col_major> bfrag[4];
            #pragma unroll
            for (int i = 0; i < 2; ++i) {
                wmma::load_matrix_sync(afrag[i], Ab + (wc + 16 * i) * SROW + kk, SROW);
            }
            #pragma unroll
            for (int j = 0; j < 4; ++j) {
                wmma::load_matrix_sync(bfrag[j], Bb + (wn + 16 * j) * SROW + kk, SROW);
            }
            #pragma unroll
            for (int i = 0; i < 2; ++i) {
                #pragma unroll
                for (int j = 0; j < 4; ++j) {
                    wmma::mma_sync(acc[i][j], afrag[i], bfrag[j], acc[i][j]);
                }
            }
        }
        __syncthreads();
    }

    const float g = 0.5f * gamma[0];
    const float* xb = x   + (size_t)b * C_ * NPIX;
    float*       ob = out + (size_t)b * C_ * NPIX;
    float* stg = (float*)(&As[0][0]) + warp * 256;

    const int srow = lane >> 1;
    const int scol = (lane & 1) * 8;

    #pragma unroll
    for (int i = 0; i < 2; ++i) {
        #pragma unroll
        for (int j = 0; j < 4; ++j) {
            wmma::store_matrix_sync(stg, acc[i][j], 16, wmma::mem_row_major);
            __syncwarp();
            const int cc = c0 + wc + 16 * i + srow;
            const int nn = n0 + wn + 16 * j + scol;
            const size_t off = (size_t)cc * NPIX + nn;
            float4 s0 = *(const float4*)&stg[srow * 16 + scol];
            float4 s1 = *(const float4*)&stg[srow * 16 + scol + 4];
            float4 xv0 = *(const float4*)&xb[off];
            float4 xv1 = *(const float4*)&xb[off + 4];
            float4 ov0;
            float4 ov1;
            ov0.x = g * s0.x + xv0.x;
            ov0.y = g * s0.y + xv0.y;
            ov0.z = g * s0.z + xv0.z;
            ov0.w = g * s0.w + xv0.w;
            ov1.x = g * s1.x + xv1.x;
            ov1.y = g * s1.y + xv1.y;
            ov1.z = g * s1.z + xv1.z;
            ov1.w = g * s1.w + xv1.w;
            *(float4*)&ob[off]     = ov0;
            *(float4*)&ob[off + 4] = ov1;
            __syncwarp();
        }
    }
}

// ---------------------------------------------------------------------------
extern "C" void kernel_launch(void* const* d_in, const int* in_sizes, int n_in,
                              void* d_out, int out_size) {
    const float* x     = (const float*)d_in[0];
    const float* Wq    = (const float*)d_in[1];
    const float* bq    = (const float*)d_in[2];
    const float* Wk    = (const float*)d_in[3];
    const float* bk    = (const float*)d_in[4];
    const float* Wv    = (const float*)d_in[5];
    const float* bv    = (const float*)d_in[6];
    const float* gamma = (const float*)d_in[7];

    float* out = (float*)d_out;
    float* att = out + (size_t)B_ * C_ * NPIX;

    proj_kernel<<<dim3(16, 5, B_), 256>>>(x, Wq, bq, Wk, bk, Wv, bv);
    fused_attn_kernel<<<dim3(32, B_), 256>>>(att);
    av_wmma_kernel<<<dim3(32, 2, B_), 256>>>(x, gamma, out);
}

// round 16
// speedup vs baseline: 1.1125x; 1.0560x over previous
#include <cuda_runtime.h>
#include <cuda_bf16.h>
#include <cuda_pipeline.h>
#include <mma.h>
#include <math.h>

#define B_    8
#define C_    256
#define NPIX  4096
#define SROW  40
#define FST   68
#define WPAD  40
#define XPAD  264

using namespace nvcuda;

// q hi rows [0,32), k hi [32,64), q lo [64,96), k lo [96,128)
__device__ __nv_bfloat16  g_qkb[(size_t)B_ * 128 * NPIX];
__device__ __nv_bfloat16  g_vb[(size_t)B_ * C_ * NPIX];
__device__ __nv_bfloat16  g_attb[(size_t)B_ * NPIX * NPIX];

// ---------------------------------------------------------------------------
// K1: QKV projection on tensor cores via split-bf16 (R15, unchanged).
// ---------------------------------------------------------------------------
__global__ void __launch_bounds__(256, 2)
proj_kernel(const float* __restrict__ x,
            const float* __restrict__ Wq, const float* __restrict__ bq,
            const float* __restrict__ Wk, const float* __restrict__ bk,
            const float* __restrict__ Wv, const float* __restrict__ bv) {
    __shared__ __align__(16) __nv_bfloat16 Whi[64 * WPAD];
    __shared__ __align__(16) __nv_bfloat16 Wlo[64 * WPAD];
    __shared__ __align__(16) __nv_bfloat16 Xhi[32 * XPAD];
    __shared__ __align__(16) __nv_bfloat16 Xlo[32 * XPAD];

    const int b  = blockIdx.z;
    const int o0 = blockIdx.y * 64;
    const int n0 = blockIdx.x * 256;
    const int tid  = threadIdx.x;
    const int warp = tid >> 5;
    const int lane = tid & 31;
    const int wo = (warp & 1) * 32;
    const int wn = (warp >> 1) * 64;

    const float* xb = x + (size_t)b * C_ * NPIX;

    wmma::fragment<wmma::accumulator, 16, 16, 16, float> acc[2][4];
    #pragma unroll
    for (int i = 0; i < 2; ++i) {
        #pragma unroll
        for (int j = 0; j < 4; ++j) wmma::fill_fragment(acc[i][j], 0.0f);
    }

    for (int k0 = 0; k0 < C_; k0 += 32) {
        {
            const int wrow = tid >> 2;
            const int wk = (tid & 3) * 8;
            const int go = o0 + wrow;
            const float* Wrow;
            if (go < 32) {
                Wrow = Wq + go * C_;
            } else if (go < 64) {
                Wrow = Wk + (go - 32) * C_;
            } else {
                Wrow = Wv + (go - 64) * C_;
            }
            #pragma unroll
            for (int u = 0; u < 8; ++u) {
                float v = Wrow[k0 + wk + u];
                __nv_bfloat16 h = __float2bfloat16(v);
                Whi[wrow * WPAD + wk + u] = h;
                Wlo[wrow * WPAD + wk + u] = __float2bfloat16(v - __bfloat162float(h));
            }
        }
        {
            const int kk = tid >> 3;
            const int nj = (tid & 7) * 32;
            const float* xr = xb + (size_t)(k0 + kk) * NPIX + n0 + nj;
            __nv_bfloat16* dh = &Xhi[kk * XPAD + nj];
            __nv_bfloat16* dl = &Xlo[kk * XPAD + nj];
            #pragma unroll
            for (int u = 0; u < 8; ++u) {
                float4 v4 = *(const float4*)(xr + u * 4);
                float vv[4];
                vv[0] = v4.x; vv[1] = v4.y; vv[2] = v4.z; vv[3] = v4.w;
                #pragma unroll
                for (int e = 0; e < 4; ++e) {
                    __nv_bfloat16 h = __float2bfloat16(vv[e]);
                    dh[u * 4 + e] = h;
                    dl[u * 4 + e] = __float2bfloat16(vv[e] - __bfloat162float(h));
                }
            }
        }
        __syncthreads();

        #pragma unroll
        for (int kc = 0; kc < 2; ++kc) {
            wmma::fragment<wmma::matrix_a, 16, 16, 16, __nv_bfloat16, wmma::row_major> ah[2], al[2];
            wmma::fragment<wmma::matrix_b, 16, 16, 16, __nv_bfloat16, wmma::row_major> bh[4], bl[4];
            #pragma unroll
            for (int i = 0; i < 2; ++i) {
                wmma::load_matrix_sync(ah[i], &Whi[(wo + 16 * i) * WPAD + kc * 16], WPAD);
                wmma::load_matrix_sync(al[i], &Wlo[(wo + 16 * i) * WPAD + kc * 16], WPAD);
            }
            #pragma unroll
            for (int j = 0; j < 4; ++j) {
                wmma::load_matrix_sync(bh[j], &Xhi[(kc * 16) * XPAD + wn + 16 * j], XPAD);
                wmma::load_matrix_sync(bl[j], &Xlo[(kc * 16) * XPAD + wn + 16 * j], XPAD);
            }
            #pragma unroll
            for (int i = 0; i < 2; ++i) {
                #pragma unroll
                for (int j = 0; j < 4; ++j) {
                    wmma::mma_sync(acc[i][j], ah[i], bl[j], acc[i][j]);
                    wmma::mma_sync(acc[i][j], al[i], bh[j], acc[i][j]);
                    wmma::mma_sync(acc[i][j], ah[i], bh[j], acc[i][j]);
                }
            }
        }
        __syncthreads();
    }

    float* stg = (float*)Xhi + warp * 256;
    const int srow = lane >> 1;
    const int scol = (lane & 1) * 8;

    #pragma unroll
    for (int i = 0; i < 2; ++i) {
        #pragma unroll
        for (int j = 0; j < 4; ++j) {
            wmma::store_matrix_sync(stg, acc[i][j], 16, wmma::mem_row_major);
            __syncwarp();
            const int o = o0 + wo + 16 * i + srow;
            float bias;
            if (o < 32) {
                bias = bq[o];
            } else if (o < 64) {
                bias = bk[o - 32];
            } else {
                bias = bv[o - 64];
            }
            const int nn = n0 + wn + 16 * j + scol;
            if (o < 64) {
                __nv_bfloat16* dhi = g_qkb + ((size_t)b * 128 + o) * NPIX + nn;
                __nv_bfloat16* dlo = dhi + (size_t)64 * NPIX;
                __align__(16) __nv_bfloat16 hv[8];
                __align__(16) __nv_bfloat16 lv[8];
                #pragma unroll
                for (int e = 0; e < 8; ++e) {
                    float val = stg[srow * 16 + scol + e] + bias;
                    __nv_bfloat16 h = __float2bfloat16(val);
                    hv[e] = h;
                    lv[e] = __float2bfloat16(val - __bfloat162float(h));
                }
                *(uint4*)dhi = *(const uint4*)hv;
                *(uint4*)dlo = *(const uint4*)lv;
            } else {
                __nv_bfloat16* dst = g_vb + ((size_t)b * C_ + (o - 64)) * NPIX + nn;
                __align__(16) __nv_bfloat16 hv[8];
                #pragma unroll
                for (int e = 0; e < 8; ++e) {
                    hv[e] = __float2bfloat16(stg[srow * 16 + scol + e] + bias);
                }
                *(uint4*)dst = *(const uint4*)hv;
            }
            __syncwarp();
        }
    }
}

// ---------------------------------------------------------------------------
// K2: FUSED energy + softmax v3.
// Pass 1 computes row sums of exp(energy) ENTIRELY IN REGISTERS using the
// sm_80+ accumulator-fragment row mapping (x0,x1,x4,x5 -> row lane>>2;
// x2,x3,x6,x7 -> row (lane>>2)+8). No smem staging in pass 1.
// Pass 2 unchanged from v2 (staged, coalesced writes).
// ---------------------------------------------------------------------------
__global__ void __launch_bounds__(256, 2)
fused_attn_kernel(float* __restrict__ att) {
    __shared__ __align__(16) float stage[8][32 * FST];
    __shared__ float partsum[8][32];
    __shared__ float rowinv[128];

    const int b  = blockIdx.y;
    const int n0 = blockIdx.x * 128;
    const int warp = threadIdx.x >> 5;
    const int lane = threadIdx.x & 31;
    const int wn = (warp & 3) * 32;
    const int wm = (warp >> 2) * 64;

    const __nv_bfloat16* qh = g_qkb + (size_t)b * 128 * NPIX;
    const __nv_bfloat16* kh = qh + (size_t)32 * NPIX;
    const __nv_bfloat16* ql = qh + (size_t)64 * NPIX;
    const __nv_bfloat16* kl = qh + (size_t)96 * NPIX;

    float* st = stage[warp];

    wmma::fragment<wmma::matrix_a, 16, 16, 16, __nv_bfloat16, wmma::col_major> ah[2][2], al[2][2];
    #pragma unroll
    for (int ks = 0; ks < 2; ++ks) {
        #pragma unroll
        for (int i = 0; i < 2; ++i) {
            wmma::load_matrix_sync(ah[ks][i], qh + (size_t)(ks * 16) * NPIX + n0 + wn + 16 * i, NPIX);
            wmma::load_matrix_sync(al[ks][i], ql + (size_t)(ks * 16) * NPIX + n0 + wn + 16 * i, NPIX);
        }
    }

    // ---------------- PASS 1: register-resident row sums ----------------
    float rs[4];
    rs[0] = 0.f; rs[1] = 0.f; rs[2] = 0.f; rs[3] = 0.f;

    for (int mt = 0; mt < 32; ++mt) {
        const int m0 = mt * 128;
        wmma::fragment<wmma::accumulator, 16, 16, 16, float> acc[2][4];
        #pragma unroll
        for (int i = 0; i < 2; ++i) {
            #pragma unroll
            for (int j = 0; j < 4; ++j) wmma::fill_fragment(acc[i][j], 0.0f);
        }
        #pragma unroll
        for (int ks = 0; ks < 2; ++ks) {
            wmma::fragment<wmma::matrix_b, 16, 16, 16, __nv_bfloat16, wmma::row_major> bh[4], bl[4];
            #pragma unroll
            for (int j = 0; j < 4; ++j) {
                wmma::load_matrix_sync(bh[j], kh + (size_t)(ks * 16) * NPIX + m0 + wm + 16 * j, NPIX);
                wmma::load_matrix_sync(bl[j], kl + (size_t)(ks * 16) * NPIX + m0 + wm + 16 * j, NPIX);
            }
            #pragma unroll
            for (int i = 0; i < 2; ++i) {
                #pragma unroll
                for (int j = 0; j < 4; ++j) {
                    wmma::mma_sync(acc[i][j], ah[ks][i], bl[j], acc[i][j]);
                    wmma::mma_sync(acc[i][j], al[ks][i], bh[j], acc[i][j]);
                    wmma::mma_sync(acc[i][j], ah[ks][i], bh[j], acc[i][j]);
                }
            }
        }
        #pragma unroll
        for (int i = 0; i < 2; ++i) {
            float p0 = 0.f;
            float p1 = 0.f;
            #pragma unroll
            for (int j = 0; j < 4; ++j) {
                p0 += __expf(acc[i][j].x[0]) + __expf(acc[i][j].x[1])
                    + __expf(acc[i][j].x[4]) + __expf(acc[i][j].x[5]);
                p1 += __expf(acc[i][j].x[2]) + __expf(acc[i][j].x[3])
                    + __expf(acc[i][j].x[6]) + __expf(acc[i][j].x[7]);
            }
            rs[2 * i]     += p0;
            rs[2 * i + 1] += p1;
        }
    }
    #pragma unroll
    for (int u = 0; u < 4; ++u) {
        rs[u] += __shfl_xor_sync(0xFFFFFFFFu, rs[u], 1);
        rs[u] += __shfl_xor_sync(0xFFFFFFFFu, rs[u], 2);
    }
    if ((lane & 3) == 0) {
        const int r = lane >> 2;
        partsum[warp][r]      = rs[0];
        partsum[warp][8 + r]  = rs[1];
        partsum[warp][16 + r] = rs[2];
        partsum[warp][24 + r] = rs[3];
    }
    __syncthreads();
    if (warp < 4) {
        float tot = partsum[warp][lane] + partsum[warp + 4][lane];
        rowinv[wn + lane] = 1.0f / tot;
    }
    __syncthreads();

    float* ab = att + ((size_t)b * NPIX + n0) * NPIX;
    __nv_bfloat16* abb = g_attb + ((size_t)b * NPIX + n0) * NPIX;

    // ---------------- PASS 2: recompute, scale, write (v2, unchanged) ----
    for (int mt = 0; mt < 32; ++mt) {
        const int m0 = mt * 128;
        wmma::fragment<wmma::accumulator, 16, 16, 16, float> acc[2][4];
        #pragma unroll
        for (int i = 0; i < 2; ++i) {
            #pragma unroll
            for (int j = 0; j < 4; ++j) wmma::fill_fragment(acc[i][j], 0.0f);
        }
        #pragma unroll
        for (int ks = 0; ks < 2; ++ks) {
            wmma::fragment<wmma::matrix_b, 16, 16, 16, __nv_bfloat16, wmma::row_major> bh[4], bl[4];
            #pragma unroll
            for (int j = 0; j < 4; ++j) {
                wmma::load_matrix_sync(bh[j], kh + (size_t)(ks * 16) * NPIX + m0 + wm + 16 * j, NPIX);
                wmma::load_matrix_sync(bl[j], kl + (size_t)(ks * 16) * NPIX + m0 + wm + 16 * j, NPIX);
            }
            #pragma unroll
            for (int i = 0; i < 2; ++i) {
                #pragma unroll
                for (int j = 0; j < 4; ++j) {
                    wmma::mma_sync(acc[i][j], ah[ks][i], bl[j], acc[i][j]);
                    wmma::mma_sync(acc[i][j], al[ks][i], bh[j], acc[i][j]);
                    wmma::mma_sync(acc[i][j], ah[ks][i], bh[j], acc[i][j]);
                }
            }
        }
        #pragma unroll
        for (int i = 0; i < 2; ++i) {
            #pragma unroll
            for (int j = 0; j < 4; ++j) {
                wmma::store_matrix_sync(st + (16 * i) * FST + 16 * j, acc[i][j],
                                        FST, wmma::mem_row_major);
            }
        }
        __syncwarp();
        #pragma unroll 4
        for (int r = 0; r < 32; ++r) {
            const float inv = rowinv[wn + r];
            const float e0 = st[r * FST + 2 * lane];
            const float e1 = st[r * FST + 2 * lane + 1];
            const float p0 = __expf(e0) * inv;
            const float p1 = __expf(e1) * inv;
            const size_t off = (size_t)(wn + r) * NPIX + m0 + wm + 2 * lane;
            float2 pv;
            pv.x = p0;
            pv.y = p1;
            *(float2*)&ab[off] = pv;
            *(__nv_bfloat162*)&abb[off] = __floats2bfloat162_rn(p0, p1);
        }
        __syncwarp();
    }
}

// ---------------------------------------------------------------------------
// K3: tensor-core AV GEMM, cp.async double-buffered (R11 exact, 328us).
// ---------------------------------------------------------------------------
__global__ void __launch_bounds__(256, 2)
av_wmma_kernel(const float* __restrict__ x, const float* __restrict__ gamma,
               float* __restrict__ out) {
    __shared__ __align__(256) __nv_bfloat16 As[2][128 * SROW];
    __shared__ __align__(256) __nv_bfloat16 Bs[2][128 * SROW];

    const int b    = blockIdx.z;
    const int c0   = blockIdx.y * 128;
    const int n0   = blockIdx.x * 128;
    const int tid  = threadIdx.x;
    const int warp = tid >> 5;
    const int lane = tid & 31;
    const int wc   = (warp & 3) * 32;
    const int wn   = (warp >> 2) * 64;

    const __nv_bfloat16* vb = g_vb   + (size_t)b * C_ * NPIX;
    const __nv_bfloat16* ab = g_attb + (size_t)b * NPIX * NPIX;

    const int lrow  = tid >> 1;
    const int lhalf = (tid & 1) * 16;
    const __nv_bfloat16* gA = vb + (size_t)(c0 + lrow) * NPIX + lhalf;
    const __nv_bfloat16* gB = ab + (size_t)(n0 + lrow) * NPIX + lhalf;
    const int sOff = lrow * SROW + lhalf;

    wmma::fragment<wmma::accumulator, 16, 16, 16, float> acc[2][4];
    #pragma unroll
    for (int i = 0; i < 2; ++i) {
        #pragma unroll
        for (int j = 0; j < 4; ++j) wmma::fill_fragment(acc[i][j], 0.0f);
    }

    __pipeline_memcpy_async(&As[0][sOff],     gA,     16);
    __pipeline_memcpy_async(&As[0][sOff + 8], gA + 8, 16);
    __pipeline_memcpy_async(&Bs[0][sOff],     gB,     16);
    __pipeline_memcpy_async(&Bs[0][sOff + 8], gB + 8, 16);
    __pipeline_commit();

    for (int it = 0; it < 128; ++it) {
        const int cur = it & 1;
        const int nxt = cur ^ 1;
        if (it < 127) {
            const __nv_bfloat16* pA = gA + (it + 1) * 32;
            const __nv_bfloat16* pB = gB + (it + 1) * 32;
            __pipeline_memcpy_async(&As[nxt][sOff],     pA,     16);
            __pipeline_memcpy_async(&As[nxt][sOff + 8], pA + 8, 16);
            __pipeline_memcpy_async(&Bs[nxt][sOff],     pB,     16);
            __pipeline_memcpy_async(&Bs[nxt][sOff + 8], pB + 8, 16);
            __pipeline_commit();
            __pipeline_wait_prior(1);
        } else {
            __pipeline_wait_prior(0);
        }
        __syncthreads();

        const __nv_bfloat16* Ab = &As[cur][0];
        const __nv_bfloat16* Bb = &Bs[cur][0];

        #pragma unroll
        for (int kk = 0; kk < 32; kk += 16) {
            wmma::fragment<wmma::matrix_a, 16, 16, 16, __nv_bfloat16, wmma::row_major> afrag[2];
            wmma::fragment<wmma::matrix_b, 16, 16, 16, __nv_bfloat16, wmma::col_major> bfrag[4];
            #pragma unroll
            for (int i = 0; i < 2; ++i) {
                wmma::load_matrix_sync(afrag[i], Ab + (wc + 16 * i) * SROW + kk, SROW);
            }
            #pragma unroll
            for (int j = 0; j < 4; ++j) {
                wmma::load_matrix_sync(bfrag[j], Bb + (wn + 16 * j) * SROW + kk, SROW);
            }
            #pragma unroll
            for (int i = 0; i < 2; ++i) {
                #pragma unroll
                for (int j = 0; j < 4; ++j) {
                    wmma::mma_sync(acc[i][j], afrag[i], bfrag[j], acc[i][j]);
                }
            }
        }
        __syncthreads();
    }

    const float g = 0.5f * gamma[0];
    const float* xb = x   + (size_t)b * C_ * NPIX;
    float*       ob = out + (size_t)b * C_ * NPIX;
    float* stg = (float*)(&As[0][0]) + warp * 256;

    const int srow = lane >> 1;
    const int scol = (lane & 1) * 8;

    #pragma unroll
    for (int i = 0; i < 2; ++i) {
        #pragma unroll
        for (int j = 0; j < 4; ++j) {
            wmma::store_matrix_sync(stg, acc[i][j], 16, wmma::mem_row_major);
            __syncwarp();
            const int cc = c0 + wc + 16 * i + srow;
            const int nn = n0 + wn + 16 * j + scol;
            const size_t off = (size_t)cc * NPIX + nn;
            float4 s0 = *(const float4*)&stg[srow * 16 + scol];
            float4 s1 = *(const float4*)&stg[srow * 16 + scol + 4];
            float4 xv0 = *(const float4*)&xb[off];
            float4 xv1 = *(const float4*)&xb[off + 4];
            float4 ov0;
            float4 ov1;
            ov0.x = g * s0.x + xv0.x;
            ov0.y = g * s0.y + xv0.y;
            ov0.z = g * s0.z + xv0.z;
            ov0.w = g * s0.w + xv0.w;
            ov1.x = g * s1.x + xv1.x;
            ov1.y = g * s1.y + xv1.y;
            ov1.z = g * s1.z + xv1.z;
            ov1.w = g * s1.w + xv1.w;
            *(float4*)&ob[off]     = ov0;
            *(float4*)&ob[off + 4] = ov1;
            __syncwarp();
        }
    }
}

// ---------------------------------------------------------------------------
extern "C" void kernel_launch(void* const* d_in, const int* in_sizes, int n_in,
                              void* d_out, int out_size) {
    const float* x     = (const float*)d_in[0];
    const float* Wq    = (const float*)d_in[1];
    const float* bq    = (const float*)d_in[2];
    const float* Wk    = (const float*)d_in[3];
    const float* bk    = (const float*)d_in[4];
    const float* Wv    = (const float*)d_in[5];
    const float* bv    = (const float*)d_in[6];
    const float* gamma = (const float*)d_in[7];

    float* out = (float*)d_out;
    float* att = out + (size_t)B_ * C_ * NPIX;

    proj_kernel<<<dim3(16, 5, B_), 256>>>(x, Wq, bq, Wk, bk, Wv, bv);
    fused_attn_kernel<<<dim3(32, B_), 256>>>(att);
    av_wmma_kernel<<<dim3(32, 2, B_), 256>>>(x, gamma, out);
}